// round 6
// baseline (speedup 1.0000x reference)
#include <cuda_runtime.h>
#include <math.h>

#define EPSF 1e-8f
#define NB     64
#define NTOKP1 785
#define DIM    768
#define FH     28
#define NTOK   784
#define IMG    448
#define NCH    3
#define TOPK   8
#define PE     16
#define TGRP   7          // token groups per batch
#define TPG    112        // tokens per group (784/7)
#define ROWT   8          // output rows per crop CTA
#define SROWS  10         // staged input rows (max span for 8 rows is 9)

// scratch: per-batch distances and crop box (no allocations allowed)
__device__ float g_dist[NB][NTOK];
__device__ int   g_box[NB][4];

// ---------------------------------------------------------------------------
// Kernel A1: cosine distances. grid = (7 token-groups, 64 batches), 256 thr.
// Each warp processes TWO tokens per iteration -> 12 outstanding LDG.128,
// and the shared g-vector LDS is amortized across the pair.
// ---------------------------------------------------------------------------
__global__ __launch_bounds__(256)
void sim_kernel(const float* __restrict__ x) {
    const int grp = blockIdx.x;
    const int b   = blockIdx.y;
    const float* __restrict__ xb = x + (size_t)b * NTOKP1 * DIM;

    __shared__ float gs[DIM];
    __shared__ float red[8];

    const int tid  = threadIdx.x;
    const int lane = tid & 31;
    const int wid  = tid >> 5;

    // Load global token g into smem + sum of squares
    float ss = 0.f;
    for (int j = tid; j < DIM; j += 256) {
        float v = __ldg(xb + j);
        gs[j] = v;
        ss += v * v;
    }
    #pragma unroll
    for (int o = 16; o; o >>= 1) ss += __shfl_xor_sync(0xffffffffu, ss, o);
    if (lane == 0) red[wid] = ss;
    __syncthreads();
    if (tid == 0) {
        float s = 0.f;
        #pragma unroll
        for (int w = 0; w < 8; w++) s += red[w];
        red[0] = s;
    }
    __syncthreads();
    const float gn = fmaxf(sqrtf(red[0]), EPSF);

    // 8 warps x 7 pairs cover 112 tokens: t0 = base+16p+wid, t1 = t0+8
    const int t_base = grp * TPG;
    #pragma unroll 1
    for (int p = 0; p < 7; p++) {
        const int t0 = t_base + 16 * p + wid;
        const int t1 = t0 + 8;
        const float* __restrict__ lr0 = xb + (size_t)(t0 + 1) * DIM;
        const float* __restrict__ lr1 = xb + (size_t)(t1 + 1) * DIM;
        float dot0 = 0.f, ls0 = 0.f, dot1 = 0.f, ls1 = 0.f;
        #pragma unroll
        for (int i = 0; i < 6; i++) {
            const int j = i * 128 + lane * 4;
            const float4 a0 = *(const float4*)(lr0 + j);
            const float4 a1 = *(const float4*)(lr1 + j);
            const float4 gv = *(const float4*)(gs + j);
            dot0 += a0.x * gv.x + a0.y * gv.y + a0.z * gv.z + a0.w * gv.w;
            ls0  += a0.x * a0.x + a0.y * a0.y + a0.z * a0.z + a0.w * a0.w;
            dot1 += a1.x * gv.x + a1.y * gv.y + a1.z * gv.z + a1.w * gv.w;
            ls1  += a1.x * a1.x + a1.y * a1.y + a1.z * a1.z + a1.w * a1.w;
        }
        #pragma unroll
        for (int o = 16; o; o >>= 1) {
            dot0 += __shfl_xor_sync(0xffffffffu, dot0, o);
            ls0  += __shfl_xor_sync(0xffffffffu, ls0, o);
            dot1 += __shfl_xor_sync(0xffffffffu, dot1, o);
            ls1  += __shfl_xor_sync(0xffffffffu, ls1, o);
        }
        if (lane == 0) {
            g_dist[b][t0] = dot0 / (gn * fmaxf(sqrtf(ls0), EPSF));
            g_dist[b][t1] = dot1 / (gn * fmaxf(sqrtf(ls1), EPSF));
        }
    }
}

// ---------------------------------------------------------------------------
// Kernel A2: top-8 (ties -> lowest index, matching lax.top_k) -> crop box.
// One warp per batch.
// ---------------------------------------------------------------------------
__global__ __launch_bounds__(32)
void topk_box_kernel() {
    const int b    = blockIdx.x;
    const int lane = threadIdx.x;

    __shared__ float dist[NTOK];
    for (int t = lane; t < NTOK; t += 32) dist[t] = g_dist[b][t];
    __syncwarp();

    int minR = FH, maxR = -1, minC = FH, maxC = -1;
    for (int k = 0; k < TOPK; k++) {
        float bv = -3e38f;
        int   bi = 0x7fffffff;
        for (int t = lane; t < NTOK; t += 32) {
            const float v = dist[t];
            if (v > bv || (v == bv && t < bi)) { bv = v; bi = t; }
        }
        #pragma unroll
        for (int o = 16; o; o >>= 1) {
            const float ov = __shfl_xor_sync(0xffffffffu, bv, o);
            const int   oi = __shfl_xor_sync(0xffffffffu, bi, o);
            if (ov > bv || (ov == bv && oi < bi)) { bv = ov; bi = oi; }
        }
        if (lane == 0) dist[bi] = -3e38f;
        __syncwarp();
        const int r = bi / FH, c = bi % FH;
        minR = min(minR, r); maxR = max(maxR, r);
        minC = min(minC, c); maxC = max(maxC, c);
    }
    if (lane == 0) {
        const int x_i = minR * PE, x_f = maxR * PE;
        const int y_i = minC * PE, y_f = maxC * PE;
        const int x0 = max(x_i, 0);
        const int y0 = max(y_i, 0);
        const int x1 = min(max(x_f, x_i + PE), IMG);
        const int y1 = min(max(y_f, y_i + PE), IMG);
        g_box[b][0] = x0; g_box[b][1] = x1;
        g_box[b][2] = y0; g_box[b][3] = y1;
    }
}

// ---------------------------------------------------------------------------
// Kernel B: bilinear crop-resize (align_corners). One CTA handles an 8-row
// output tile for ALL 3 channels of one batch, with a cp.async double-buffered
// channel pipeline (stage ch c+1 while computing ch c).
// grid = (56 row-tiles, 64 batches), block = 448 threads.
// ---------------------------------------------------------------------------
__device__ __forceinline__ void stage_rows_async(
    float* sdst, const float* __restrict__ gsrc,
    int nrows, int wspan, int ox)
{
    if (ox < wspan) {
        unsigned das = (unsigned)__cvta_generic_to_shared(sdst + ox);
        const float* __restrict__ s = gsrc + ox;
        #pragma unroll 4
        for (int r = 0; r < nrows; r++) {
            asm volatile("cp.async.ca.shared.global [%0], [%1], 4;"
                         :: "r"(das + r * IMG * 4), "l"(s + (size_t)r * IMG));
        }
    }
    asm volatile("cp.async.commit_group;");
}

__global__ __launch_bounds__(IMG)
void crop_resize_kernel(const float* __restrict__ images, float* __restrict__ out) {
    __shared__ float sbuf[2][SROWS * IMG];   // 2 x 17.5 KB = 35 KB

    const int rt = blockIdx.x;           // 8-row tile
    const int b  = blockIdx.y;
    const int ox = threadIdx.x;

    const int x0 = g_box[b][0], x1 = g_box[b][1];
    const int y0 = g_box[b][2], y1 = g_box[b][3];

    const float scale = (float)(1.0 / 447.0);
    const float hm1 = __fadd_rn((float)(x1 - x0), -1.0f);
    const float wm1 = __fadd_rn((float)(y1 - y0), -1.0f);

    // Vertical input-row range covered by this tile (sy monotone in oy).
    const int oy0 = rt * ROWT;
    const float syA = __fadd_rn((float)x0, __fmul_rn(__fmul_rn((float)oy0, hm1), scale));
    const float syB = __fadd_rn((float)x0, __fmul_rn(__fmul_rn((float)(oy0 + ROWT - 1), hm1), scale));
    const int ystart = (int)floorf(syA);
    const int yloB   = (int)floorf(syB);
    const int yend   = max(yloB, min(yloB + 1, x1 - 1));
    const int nrows  = yend - ystart + 1;        // <= 9
    const int wspan  = y1 - y0;                  // needed columns [y0, y1)

    // Horizontal (per-thread, constant across rows & channels).
    // Reference fp32 expression order, no FMA contraction.
    const float sx = __fadd_rn((float)y0, __fmul_rn(__fmul_rn((float)ox, wm1), scale));
    const int   xlo = (int)floorf(sx);
    const int   xhi = min(xlo + 1, y1 - 1);
    const float wx  = __fadd_rn(sx, -(float)xlo);
    const float wx1 = 1.f - wx;
    const int   clo = xlo - y0;
    const int   chi = xhi - y0;

    const float* __restrict__ img0 = images + (size_t)b * NCH * IMG * IMG
                                   + (size_t)ystart * IMG + y0;

    // Stage channel 0
    stage_rows_async(sbuf[0], img0, nrows, wspan, ox);

    #pragma unroll
    for (int c = 0; c < NCH; c++) {
        // Issue next channel's stage before waiting (overlap with compute)
        if (c + 1 < NCH)
            stage_rows_async(sbuf[(c + 1) & 1], img0 + (size_t)(c + 1) * IMG * IMG,
                             nrows, wspan, ox);
        if (c + 1 < NCH) asm volatile("cp.async.wait_group 1;");
        else             asm volatile("cp.async.wait_group 0;");
        __syncthreads();

        const float* __restrict__ sb = sbuf[c & 1];
        float* __restrict__ op = out + ((size_t)(b * NCH + c) * IMG + oy0) * IMG + ox;

        #pragma unroll
        for (int r = 0; r < ROWT; r++) {
            const int oy = oy0 + r;
            const float sy  = __fadd_rn((float)x0, __fmul_rn(__fmul_rn((float)oy, hm1), scale));
            const int   ylo = (int)floorf(sy);
            const int   yhi = min(ylo + 1, x1 - 1);
            const float wy  = __fadd_rn(sy, -(float)ylo);
            const float wy1 = 1.f - wy;

            const float* __restrict__ s0 = sb + (ylo - ystart) * IMG;
            const float* __restrict__ s1 = sb + (yhi - ystart) * IMG;
            const float v00 = s0[clo];
            const float v01 = s0[chi];
            const float v10 = s1[clo];
            const float v11 = s1[chi];

            const float res = wy1 * wx1 * v00 + wy1 * wx * v01
                            + wy  * wx1 * v10 + wy  * wx * v11;
            op[(size_t)r * IMG] = res;
        }
        __syncthreads();   // protect buffer reuse by next iteration's stage
    }
}

// ---------------------------------------------------------------------------
extern "C" void kernel_launch(void* const* d_in, const int* in_sizes, int n_in,
                              void* d_out, int out_size) {
    const float* x      = (const float*)d_in[0];   // (64, 785, 768) fp32
    const float* images = (const float*)d_in[1];   // (64, 3, 448, 448) fp32
    float* out = (float*)d_out;                    // (64, 3, 448, 448) fp32

    dim3 gridA(TGRP, NB);
    sim_kernel<<<gridA, 256>>>(x);
    topk_box_kernel<<<NB, 32>>>();
    dim3 gridB(IMG / ROWT, NB);
    crop_resize_kernel<<<gridB, IMG>>>(images, out);
}

// round 7
// speedup vs baseline: 1.2771x; 1.2771x over previous
#include <cuda_runtime.h>
#include <math.h>

#define EPSF 1e-8f
#define NB     64
#define NTOKP1 785
#define DIM    768
#define FH     28
#define NTOK   784
#define IMG    448
#define NCH    3
#define TOPK   8
#define PE     16
#define TGRP   7          // token groups per batch
#define TPG    112        // tokens per group (784/7)
#define ROWT   16         // output rows per crop CTA
#define SROWS  18         // staged input rows (max span for 16 rows is 17)

// scratch (no allocations allowed); device globals zero-initialized
__device__ float g_dist[NB][NTOK];
__device__ int   g_box[NB][4];
__device__ int   g_cnt[NB];

// ---------------------------------------------------------------------------
// Kernel A: cosine distances + fused top-8 box (last CTA per batch).
// grid = (7 token-groups, 64 batches), 256 thr. Warp processes token pairs.
// ---------------------------------------------------------------------------
__global__ __launch_bounds__(256)
void sim_box_kernel(const float* __restrict__ x) {
    const int grp = blockIdx.x;
    const int b   = blockIdx.y;
    const float* __restrict__ xb = x + (size_t)b * NTOKP1 * DIM;

    __shared__ float gs[DIM];
    __shared__ float red[8];
    __shared__ float sdist[NTOK];
    __shared__ int   s_last;

    const int tid  = threadIdx.x;
    const int lane = tid & 31;
    const int wid  = tid >> 5;

    // Load global token g into smem + sum of squares
    float ss = 0.f;
    for (int j = tid; j < DIM; j += 256) {
        float v = __ldg(xb + j);
        gs[j] = v;
        ss += v * v;
    }
    #pragma unroll
    for (int o = 16; o; o >>= 1) ss += __shfl_xor_sync(0xffffffffu, ss, o);
    if (lane == 0) red[wid] = ss;
    __syncthreads();
    if (tid == 0) {
        float s = 0.f;
        #pragma unroll
        for (int w = 0; w < 8; w++) s += red[w];
        red[0] = s;
    }
    __syncthreads();
    const float gn = fmaxf(sqrtf(red[0]), EPSF);

    // 8 warps x 7 pairs cover 112 tokens: t0 = base+16p+wid, t1 = t0+8
    const int t_base = grp * TPG;
    #pragma unroll 1
    for (int p = 0; p < 7; p++) {
        const int t0 = t_base + 16 * p + wid;
        const int t1 = t0 + 8;
        const float* __restrict__ lr0 = xb + (size_t)(t0 + 1) * DIM;
        const float* __restrict__ lr1 = xb + (size_t)(t1 + 1) * DIM;
        float dot0 = 0.f, ls0 = 0.f, dot1 = 0.f, ls1 = 0.f;
        #pragma unroll
        for (int i = 0; i < 6; i++) {
            const int j = i * 128 + lane * 4;
            const float4 a0 = *(const float4*)(lr0 + j);
            const float4 a1 = *(const float4*)(lr1 + j);
            const float4 gv = *(const float4*)(gs + j);
            dot0 += a0.x * gv.x + a0.y * gv.y + a0.z * gv.z + a0.w * gv.w;
            ls0  += a0.x * a0.x + a0.y * a0.y + a0.z * a0.z + a0.w * a0.w;
            dot1 += a1.x * gv.x + a1.y * gv.y + a1.z * gv.z + a1.w * gv.w;
            ls1  += a1.x * a1.x + a1.y * a1.y + a1.z * a1.z + a1.w * a1.w;
        }
        #pragma unroll
        for (int o = 16; o; o >>= 1) {
            dot0 += __shfl_xor_sync(0xffffffffu, dot0, o);
            ls0  += __shfl_xor_sync(0xffffffffu, ls0, o);
            dot1 += __shfl_xor_sync(0xffffffffu, dot1, o);
            ls1  += __shfl_xor_sync(0xffffffffu, ls1, o);
        }
        if (lane == 0) {
            g_dist[b][t0] = dot0 / (gn * fmaxf(sqrtf(ls0), EPSF));
            g_dist[b][t1] = dot1 / (gn * fmaxf(sqrtf(ls1), EPSF));
        }
    }

    // ---- last-CTA-per-batch does top-8 + box ----
    __threadfence();          // publish this CTA's g_dist writes
    __syncthreads();
    if (tid == 0) {
        const int old = atomicAdd(&g_cnt[b], 1);
        s_last = (old == TGRP - 1);
        if (s_last) atomicExch(&g_cnt[b], 0);   // reset for next graph replay
    }
    __syncthreads();
    if (!s_last) return;
    if (wid != 0) return;

    __threadfence();          // acquire side: order loads after the atomic
    for (int t = lane; t < NTOK; t += 32) sdist[t] = g_dist[b][t];
    __syncwarp();

    int minR = FH, maxR = -1, minC = FH, maxC = -1;
    for (int k = 0; k < TOPK; k++) {
        float bv = -3e38f;
        int   bi = 0x7fffffff;
        for (int t = lane; t < NTOK; t += 32) {
            const float v = sdist[t];
            if (v > bv || (v == bv && t < bi)) { bv = v; bi = t; }
        }
        #pragma unroll
        for (int o = 16; o; o >>= 1) {
            const float ov = __shfl_xor_sync(0xffffffffu, bv, o);
            const int   oi = __shfl_xor_sync(0xffffffffu, bi, o);
            if (ov > bv || (ov == bv && oi < bi)) { bv = ov; bi = oi; }
        }
        if (lane == 0) sdist[bi] = -3e38f;
        __syncwarp();
        const int r = bi / FH, c = bi % FH;
        minR = min(minR, r); maxR = max(maxR, r);
        minC = min(minC, c); maxC = max(maxC, c);
    }
    if (lane == 0) {
        const int x_i = minR * PE, x_f = maxR * PE;
        const int y_i = minC * PE, y_f = maxC * PE;
        g_box[b][0] = max(x_i, 0);
        g_box[b][1] = min(max(x_f, x_i + PE), IMG);
        g_box[b][2] = max(y_i, 0);
        g_box[b][3] = min(max(y_f, y_i + PE), IMG);
    }
}

// ---------------------------------------------------------------------------
// Kernel B: bilinear crop-resize (align_corners), 16 output rows per CTA.
// Staging via 16B cp.async (y0/y1 are multiples of 16 -> float4-aligned span).
// grid = (28 row-tiles, 3 channels, 64 batches), block = 448 threads.
// ---------------------------------------------------------------------------
__global__ __launch_bounds__(IMG)
void crop_resize_kernel(const float* __restrict__ images, float* __restrict__ out) {
    __shared__ __align__(16) float srows[SROWS * IMG];   // 32.25 KB

    const int rt = blockIdx.x;           // row tile
    const int c  = blockIdx.y;
    const int b  = blockIdx.z;
    const int ox = threadIdx.x;

    const int x0 = g_box[b][0], x1 = g_box[b][1];
    const int y0 = g_box[b][2], y1 = g_box[b][3];

    const float scale = (float)(1.0 / 447.0);
    const float hm1 = __fadd_rn((float)(x1 - x0), -1.0f);
    const float wm1 = __fadd_rn((float)(y1 - y0), -1.0f);

    // Vertical input-row range covered by this tile (sy monotone in oy).
    const int oy0 = rt * ROWT;
    const float syA = __fadd_rn((float)x0, __fmul_rn(__fmul_rn((float)oy0, hm1), scale));
    const float syB = __fadd_rn((float)x0, __fmul_rn(__fmul_rn((float)(oy0 + ROWT - 1), hm1), scale));
    const int ystart = (int)floorf(syA);
    const int yloB   = (int)floorf(syB);
    const int yend   = max(yloB, min(yloB + 1, x1 - 1));
    const int nrows  = yend - ystart + 1;        // <= 18
    const int wspan  = y1 - y0;                  // multiple of 16

    // Stage rows with 16B cp.async: wspan/4 <= 112 threads, each loads a
    // float4 column slice of every row. Perfectly aligned (y0 mult of 16).
    const float* __restrict__ img = images + (size_t)(b * NCH + c) * IMG * IMG;
    const int nthr4 = wspan >> 2;
    if (ox < nthr4) {
        unsigned das = (unsigned)__cvta_generic_to_shared(srows) + ox * 16;
        const float* __restrict__ src = img + (size_t)ystart * IMG + y0 + ox * 4;
        #pragma unroll 3
        for (int r = 0; r < nrows; r++) {
            asm volatile("cp.async.cg.shared.global [%0], [%1], 16;"
                         :: "r"(das + r * IMG * 4), "l"(src + (size_t)r * IMG));
        }
    }
    asm volatile("cp.async.commit_group;");

    // Horizontal coords (per-thread, row-invariant) — overlap staging flight.
    // Reference fp32 expression order, no FMA contraction.
    const float sx = __fadd_rn((float)y0, __fmul_rn(__fmul_rn((float)ox, wm1), scale));
    const int   xlo = (int)floorf(sx);
    const int   xhi = min(xlo + 1, y1 - 1);
    const float wx  = __fadd_rn(sx, -(float)xlo);
    const float wx1 = 1.f - wx;
    const int   clo = xlo - y0;
    const int   chi = xhi - y0;

    asm volatile("cp.async.wait_group 0;");
    __syncthreads();

    float* __restrict__ op = out + ((size_t)(b * NCH + c) * IMG + oy0) * IMG + ox;

    #pragma unroll 4
    for (int r = 0; r < ROWT; r++) {
        const int oy = oy0 + r;
        const float sy  = __fadd_rn((float)x0, __fmul_rn(__fmul_rn((float)oy, hm1), scale));
        const int   ylo = (int)floorf(sy);
        const int   yhi = min(ylo + 1, x1 - 1);
        const float wy  = __fadd_rn(sy, -(float)ylo);
        const float wy1 = 1.f - wy;

        const float* __restrict__ s0 = srows + (ylo - ystart) * IMG;
        const float* __restrict__ s1 = srows + (yhi - ystart) * IMG;
        const float v00 = s0[clo];
        const float v01 = s0[chi];
        const float v10 = s1[clo];
        const float v11 = s1[chi];

        const float res = wy1 * wx1 * v00 + wy1 * wx * v01
                        + wy  * wx1 * v10 + wy  * wx * v11;
        __stcs(op + (size_t)r * IMG, res);   // streaming store: never re-read
    }
}

// ---------------------------------------------------------------------------
extern "C" void kernel_launch(void* const* d_in, const int* in_sizes, int n_in,
                              void* d_out, int out_size) {
    const float* x      = (const float*)d_in[0];   // (64, 785, 768) fp32
    const float* images = (const float*)d_in[1];   // (64, 3, 448, 448) fp32
    float* out = (float*)d_out;                    // (64, 3, 448, 448) fp32

    dim3 gridA(TGRP, NB);
    sim_box_kernel<<<gridA, 256>>>(x);
    dim3 gridB(IMG / ROWT, NCH, NB);
    crop_resize_kernel<<<gridB, IMG>>>(images, out);
}

// round 8
// speedup vs baseline: 1.3614x; 1.0660x over previous
#include <cuda_runtime.h>
#include <math.h>

#define EPSF 1e-8f
#define NB     64
#define NTOKP1 785
#define DIM    768
#define FH     28
#define NTOK   784
#define IMG    448
#define NCH    3
#define TOPK   8
#define PE     16
#define TGRP   7          // token groups per batch
#define TPG    112        // tokens per group (784/7)
#define ROWT   16         // output rows per crop CTA
#define SROWS  18         // staged input rows (max span for 16 rows is 17)

// scratch (no allocations allowed); device globals zero-initialized
__device__ float g_dist[NB][NTOK];
__device__ int   g_box[NB][4];
__device__ int   g_cnt[NB];

// ---------------------------------------------------------------------------
// Kernel A: cosine distances + fused top-8 box (last CTA per batch).
// grid = (7 token-groups, 64 batches), 256 thr. Warp processes token pairs.
// ---------------------------------------------------------------------------
__global__ __launch_bounds__(256)
void sim_box_kernel(const float* __restrict__ x) {
    const int grp = blockIdx.x;
    const int b   = blockIdx.y;
    const float* __restrict__ xb = x + (size_t)b * NTOKP1 * DIM;

    __shared__ float gs[DIM];
    __shared__ float red[8];
    __shared__ float sdist[NTOK];
    __shared__ int   s_last;

    const int tid  = threadIdx.x;
    const int lane = tid & 31;
    const int wid  = tid >> 5;

    // Load global token g into smem + sum of squares
    float ss = 0.f;
    for (int j = tid; j < DIM; j += 256) {
        float v = __ldg(xb + j);
        gs[j] = v;
        ss += v * v;
    }
    #pragma unroll
    for (int o = 16; o; o >>= 1) ss += __shfl_xor_sync(0xffffffffu, ss, o);
    if (lane == 0) red[wid] = ss;
    __syncthreads();
    if (tid == 0) {
        float s = 0.f;
        #pragma unroll
        for (int w = 0; w < 8; w++) s += red[w];
        red[0] = s;
    }
    __syncthreads();
    const float gn = fmaxf(sqrtf(red[0]), EPSF);

    // 8 warps x 7 pairs cover 112 tokens: t0 = base+16p+wid, t1 = t0+8
    const int t_base = grp * TPG;
    #pragma unroll 1
    for (int p = 0; p < 7; p++) {
        const int t0 = t_base + 16 * p + wid;
        const int t1 = t0 + 8;
        const float* __restrict__ lr0 = xb + (size_t)(t0 + 1) * DIM;
        const float* __restrict__ lr1 = xb + (size_t)(t1 + 1) * DIM;
        float dot0 = 0.f, ls0 = 0.f, dot1 = 0.f, ls1 = 0.f;
        #pragma unroll
        for (int i = 0; i < 6; i++) {
            const int j = i * 128 + lane * 4;
            const float4 a0 = __ldcs((const float4*)(lr0 + j));   // read-once
            const float4 a1 = __ldcs((const float4*)(lr1 + j));
            const float4 gv = *(const float4*)(gs + j);
            dot0 += a0.x * gv.x + a0.y * gv.y + a0.z * gv.z + a0.w * gv.w;
            ls0  += a0.x * a0.x + a0.y * a0.y + a0.z * a0.z + a0.w * a0.w;
            dot1 += a1.x * gv.x + a1.y * gv.y + a1.z * gv.z + a1.w * gv.w;
            ls1  += a1.x * a1.x + a1.y * a1.y + a1.z * a1.z + a1.w * a1.w;
        }
        #pragma unroll
        for (int o = 16; o; o >>= 1) {
            dot0 += __shfl_xor_sync(0xffffffffu, dot0, o);
            ls0  += __shfl_xor_sync(0xffffffffu, ls0, o);
            dot1 += __shfl_xor_sync(0xffffffffu, dot1, o);
            ls1  += __shfl_xor_sync(0xffffffffu, ls1, o);
        }
        if (lane == 0) {
            g_dist[b][t0] = dot0 / (gn * fmaxf(sqrtf(ls0), EPSF));
            g_dist[b][t1] = dot1 / (gn * fmaxf(sqrtf(ls1), EPSF));
        }
    }

    // ---- last-CTA-per-batch does top-8 + box ----
    __threadfence();          // publish this CTA's g_dist writes
    __syncthreads();
    if (tid == 0) {
        const int old = atomicAdd(&g_cnt[b], 1);
        s_last = (old == TGRP - 1);
        if (s_last) atomicExch(&g_cnt[b], 0);   // reset for next graph replay
    }
    __syncthreads();
    if (!s_last) return;
    if (wid != 0) return;

    __threadfence();          // acquire side: order loads after the atomic
    for (int t = lane; t < NTOK; t += 32) sdist[t] = g_dist[b][t];
    __syncwarp();

    int minR = FH, maxR = -1, minC = FH, maxC = -1;
    for (int k = 0; k < TOPK; k++) {
        float bv = -3e38f;
        int   bi = 0x7fffffff;
        for (int t = lane; t < NTOK; t += 32) {
            const float v = sdist[t];
            if (v > bv || (v == bv && t < bi)) { bv = v; bi = t; }
        }
        #pragma unroll
        for (int o = 16; o; o >>= 1) {
            const float ov = __shfl_xor_sync(0xffffffffu, bv, o);
            const int   oi = __shfl_xor_sync(0xffffffffu, bi, o);
            if (ov > bv || (ov == bv && oi < bi)) { bv = ov; bi = oi; }
        }
        if (lane == 0) sdist[bi] = -3e38f;
        __syncwarp();
        const int r = bi / FH, c = bi % FH;
        minR = min(minR, r); maxR = max(maxR, r);
        minC = min(minC, c); maxC = max(maxC, c);
    }
    if (lane == 0) {
        const int x_i = minR * PE, x_f = maxR * PE;
        const int y_i = minC * PE, y_f = maxC * PE;
        g_box[b][0] = max(x_i, 0);
        g_box[b][1] = min(max(x_f, x_i + PE), IMG);
        g_box[b][2] = max(y_i, 0);
        g_box[b][3] = min(max(y_f, y_i + PE), IMG);
    }
}

// ---------------------------------------------------------------------------
// Kernel B: bilinear crop-resize (align_corners), 16 output rows per CTA.
// 16B cp.async staging; vertical coords precomputed once into smem by 16
// threads (they are thread-invariant); factored lerp in the hot loop.
// grid = (28 row-tiles, 3 channels, 64 batches), block = 448 threads.
// ---------------------------------------------------------------------------
__global__ __launch_bounds__(IMG)
void crop_resize_kernel(const float* __restrict__ images, float* __restrict__ out) {
    __shared__ __align__(16) float srows[SROWS * IMG];   // 32.25 KB
    __shared__ int2  soff[ROWT];   // per-row {s0_float_off, s1_float_off}
    __shared__ float swy[ROWT];    // per-row wy

    const int rt = blockIdx.x;           // row tile
    const int c  = blockIdx.y;
    const int b  = blockIdx.z;
    const int ox = threadIdx.x;

    const int x0 = g_box[b][0], x1 = g_box[b][1];
    const int y0 = g_box[b][2], y1 = g_box[b][3];

    const float scale = (float)(1.0 / 447.0);
    const float hm1 = __fadd_rn((float)(x1 - x0), -1.0f);
    const float wm1 = __fadd_rn((float)(y1 - y0), -1.0f);

    // Vertical input-row range covered by this tile (sy monotone in oy).
    const int oy0 = rt * ROWT;
    const float syA = __fadd_rn((float)x0, __fmul_rn(__fmul_rn((float)oy0, hm1), scale));
    const float syB = __fadd_rn((float)x0, __fmul_rn(__fmul_rn((float)(oy0 + ROWT - 1), hm1), scale));
    const int ystart = (int)floorf(syA);
    const int yloB   = (int)floorf(syB);
    const int yend   = max(yloB, min(yloB + 1, x1 - 1));
    const int nrows  = yend - ystart + 1;        // <= 18
    const int wspan  = y1 - y0;                  // multiple of 16

    // Stage rows with 16B cp.async (y0 multiple of 16 -> aligned span).
    const float* __restrict__ img = images + (size_t)(b * NCH + c) * IMG * IMG;
    const int nthr4 = wspan >> 2;
    if (ox < nthr4) {
        unsigned das = (unsigned)__cvta_generic_to_shared(srows) + ox * 16;
        const float* __restrict__ src = img + (size_t)ystart * IMG + y0 + ox * 4;
        #pragma unroll 3
        for (int r = 0; r < nrows; r++) {
            asm volatile("cp.async.cg.shared.global [%0], [%1], 16;"
                         :: "r"(das + r * IMG * 4), "l"(src + (size_t)r * IMG));
        }
    }
    asm volatile("cp.async.commit_group;");

    // Vertical coords: thread-invariant -> 16 threads compute all 16 rows.
    // Identical fp32 expressions to the reference (no FMA contraction).
    if (ox < ROWT) {
        const int oy = oy0 + ox;
        const float sy  = __fadd_rn((float)x0, __fmul_rn(__fmul_rn((float)oy, hm1), scale));
        const int   ylo = (int)floorf(sy);
        const int   yhi = min(ylo + 1, x1 - 1);
        soff[ox] = make_int2((ylo - ystart) * IMG, (yhi - ystart) * IMG);
        swy[ox]  = __fadd_rn(sy, -(float)ylo);
    }

    // Horizontal coords (per-thread, row-invariant) — overlap staging flight.
    const float sx = __fadd_rn((float)y0, __fmul_rn(__fmul_rn((float)ox, wm1), scale));
    const int   xlo = (int)floorf(sx);
    const int   xhi = min(xlo + 1, y1 - 1);
    const float wx  = __fadd_rn(sx, -(float)xlo);
    const int   clo = xlo - y0;
    const int   chi = xhi - y0;

    asm volatile("cp.async.wait_group 0;");
    __syncthreads();

    float* __restrict__ op = out + ((size_t)(b * NCH + c) * IMG + oy0) * IMG + ox;

    #pragma unroll 4
    for (int r = 0; r < ROWT; r++) {
        const int2  off = soff[r];          // broadcast LDS.64
        const float wy  = swy[r];           // broadcast LDS.32

        const float* __restrict__ s0 = srows + off.x;
        const float* __restrict__ s1 = srows + off.y;
        const float v00 = s0[clo];
        const float v01 = s0[chi];
        const float v10 = s1[clo];
        const float v11 = s1[chi];

        // factored bilinear lerp (reassociation ok: tol 1e-3 >> fp32 ulp)
        const float h0 = v00 + wx * (v01 - v00);
        const float h1 = v10 + wx * (v11 - v10);
        const float res = h0 + wy * (h1 - h0);
        __stcs(op + (size_t)r * IMG, res);   // streaming store: never re-read
    }
}

// ---------------------------------------------------------------------------
extern "C" void kernel_launch(void* const* d_in, const int* in_sizes, int n_in,
                              void* d_out, int out_size) {
    const float* x      = (const float*)d_in[0];   // (64, 785, 768) fp32
    const float* images = (const float*)d_in[1];   // (64, 3, 448, 448) fp32
    float* out = (float*)d_out;                    // (64, 3, 448, 448) fp32

    dim3 gridA(TGRP, NB);
    sim_box_kernel<<<gridA, 256>>>(x);
    dim3 gridB(IMG / ROWT, NCH, NB);
    crop_resize_kernel<<<gridB, IMG>>>(images, out);
}